// round 16
// baseline (speedup 1.0000x reference)
#include <cuda_runtime.h>
#include <cuda_bf16.h>
#include <cstdint>

// Problem constants (fixed by setup_inputs)
#define B_   8
#define NCH  32      // centers channels
#define N_   16      // gaussians per (b,k)
#define K_   16
#define H_   128
#define W_   128
#define BK_  (B_ * K_)          // 128
#define HW_  (H_ * W_)          // 16384
#define NPIX ((long long)BK_ * HW_)  // 2097152

#define BLOCKS_PER_BK 2
#define ROWS_PER_BLK  (H_ / BLOCKS_PER_BK)   // 64
#define GRID_ (BK_ * BLOCKS_PER_BK)          // 256 -> 2 blocks/SM co-resident

#define LOG2E_F 1.4426950408889634f
#define LN2_F   0.6931471805599453f

// Cross-block accumulator (zero-initialized at module load; reset in-kernel).
__device__ double   g_acc;     // sum of BCE terms (negative values)
__device__ unsigned g_count;

// Packed f32x2 helpers (ptxas never emits FFMA2 from C++; PTX-only).
__device__ __forceinline__ unsigned long long pk2(float lo, float hi) {
    unsigned long long d;
    asm("mov.b64 %0, {%1, %2};" : "=l"(d) : "f"(lo), "f"(hi));
    return d;
}
__device__ __forceinline__ void upk2(float& lo, float& hi, unsigned long long v) {
    asm("mov.b64 {%0, %1}, %2;" : "=f"(lo), "=f"(hi) : "l"(v));
}
__device__ __forceinline__ unsigned long long fma2(unsigned long long a,
                                                   unsigned long long b,
                                                   unsigned long long c) {
    unsigned long long d;
    asm("fma.rn.f32x2 %0, %1, %2, %3;" : "=l"(d) : "l"(a), "l"(b), "l"(c));
    return d;
}
__device__ __forceinline__ unsigned long long add2(unsigned long long a,
                                                   unsigned long long b) {
    unsigned long long d;
    asm("add.rn.f32x2 %0, %1, %2;" : "=l"(d) : "l"(a), "l"(b));
    return d;
}

// ---------------------------------------------------------------------------
// R16: occupancy-doubled variant. Block = half a (b,k) (64 rows), 1024
// threads, 8 px/thread, __launch_bounds__(1024,2) caps regs at 32 so TWO
// blocks co-reside per SM (~55 warps/SM vs 27 in all prior rounds — the one
// axis never tested). fx kept packed in 16 regs; targets read in-loop
// (register diet). Math identical to R8:
//   g = sum_n fy[y][n]*fx[n][x] (packed FFMA2), p = sigmoid(g), masked BCE,
//   term = y*log(p*m)+(1-y*m)*log(1-p*m) (<=0); loss = -g_acc/NPIX.
// Fast path (m==1): h=-log2e*g, e=2^h, sp2=log2(1+e),
//   term = -ln2*((t-1)*h + sp2).
// ---------------------------------------------------------------------------
__global__ void __launch_bounds__(1024, 2) gl_fused(
        const float* __restrict__ centers,
        const float* __restrict__ radius,
        const float* __restrict__ mask,
        const int*   __restrict__ ind,
        const float* __restrict__ target,
        const float* __restrict__ peak,
        float* __restrict__ out, int out_n) {
    int blk  = blockIdx.x;
    int bk   = blk >> 1;
    int half = blk & 1;
    int tid  = threadIdx.x;
    int x    = tid & 127;
    int ygrp = tid >> 7;            // 0..7, warp-uniform
    int b    = bk >> 4;

    // 16-byte alignment: s_fy is read via 128-bit LDS.
    __shared__ __align__(16) float s_fx[N_ * W_];            // [n][x]   8 KB
    __shared__ __align__(16) float s_fy[ROWS_PER_BLK * N_];  // [row][n] 4 KB
    __shared__ __align__(16) float s_c[32];                  // cx,cy per n
    __shared__ float s_inv;
    __shared__ float s_wsum[32];
    __shared__ int   s_last;

    int p = ind[bk];
    if (tid < 32) {
        // channel tid of gathered pred, shifted by peak (x even, y odd)
        s_c[tid] = centers[(b * NCH + tid) * HW_ + p] + peak[bk * 2 + (tid & 1)];
    }
    if (tid == 0) {
        float r = radius[b * HW_ + p];
        s_inv = -0.5f / (r * r);
    }
    __syncthreads();

    float inv = s_inv;
    // fx: 2048 entries, 2 per thread
#pragma unroll
    for (int i = tid; i < N_ * W_; i += 1024) {
        int n  = i >> 7;
        int xx = i & 127;
        float d = s_c[2 * n] - (float)xx;
        s_fx[i] = __expf(inv * d * d);
    }
    // fy: 1024 entries (64 rows x 16), 1 per thread, layout [row][n]
    {
        int row = tid >> 4;
        int n   = tid & 15;
        float d = s_c[2 * n + 1] - (float)(half * ROWS_PER_BLK + row);
        s_fy[tid] = __expf(inv * d * d);
    }
    __syncthreads();

    // fx pre-packed into 8 f32x2 pairs (n, n+1) — 16 registers
    unsigned long long fx2[8];
#pragma unroll
    for (int j = 0; j < 8; j++)
        fx2[j] = pk2(s_fx[(2 * j) * W_ + x], s_fx[(2 * j + 1) * W_ + x]);

    float m = mask[bk];
    // this thread's 8 rows: local rows ygrp*8 .. ygrp*8+7
    const float* tg = target + (long long)bk * HW_
                    + (half * ROWS_PER_BLK + ygrp * 8) * W_ + x;
    const float* fyb = &s_fy[(ygrp * 8) * N_];

    float acc = 0.0f;   // sum of terms (negative)
    if (m == 1.0f) {
        // ---- fast path: packed dot + base-2 epilogue; t loaded in-loop ----
#pragma unroll
        for (int it = 0; it < 8; it++) {
            const ulonglong2* fyp = (const ulonglong2*)&fyb[it * N_];
            unsigned long long d0 = 0ull, d1 = 0ull, d2 = 0ull, d3 = 0ull;
            ulonglong2 w0 = fyp[0];
            ulonglong2 w1 = fyp[1];
            ulonglong2 w2 = fyp[2];
            ulonglong2 w3 = fyp[3];
            d0 = fma2(w0.x, fx2[0], d0);
            d1 = fma2(w0.y, fx2[1], d1);
            d2 = fma2(w1.x, fx2[2], d2);
            d3 = fma2(w1.y, fx2[3], d3);
            d0 = fma2(w2.x, fx2[4], d0);
            d1 = fma2(w2.y, fx2[5], d1);
            d2 = fma2(w3.x, fx2[6], d2);
            d3 = fma2(w3.y, fx2[7], d3);
            d0 = add2(d0, d1);
            d2 = add2(d2, d3);
            d0 = add2(d0, d2);
            float glo, ghi;
            upk2(glo, ghi, d0);
            float g = glo + ghi;                 // g > 0

            float t = tg[it * W_];               // in-loop LDG (reg diet)

            // base-2 epilogue: h = -log2e*g; e = 2^h; sp2 = log2(1+e)
            float h = -LOG2E_F * g;
            float e = exp2f(h);                  // MUFU.EX2
            float sp2 = __log2f(1.0f + e);       // MUFU.LG2
            // term = -ln2*(sp2 - (1-t)*h) = -ln2*fmaf(t-1, h, sp2)
            float w = fmaf(t - 1.0f, h, sp2);
            acc = fmaf(-LN2_F, w, acc);
        }
    } else {
        // ---- general path (matches reference construction exactly) ----
#pragma unroll
        for (int it = 0; it < 8; it++) {
            const float4* fy4 = (const float4*)&fyb[it * N_];
            float g0 = 0.f, g1 = 0.f, g2 = 0.f, g3 = 0.f;
#pragma unroll
            for (int q = 0; q < 4; q++) {
                float4 v = fy4[q];
                float a0, a1;
                upk2(a0, a1, fx2[q * 2]);
                g0 = fmaf(v.x, a0, g0);
                g1 = fmaf(v.y, a1, g1);
                upk2(a0, a1, fx2[q * 2 + 1]);
                g2 = fmaf(v.z, a0, g2);
                g3 = fmaf(v.w, a1, g3);
            }
            float g = (g0 + g1) + (g2 + g3);
            float e  = __expf(-g);
            float pr = 1.0f / (1.0f + e);
            float xm = pr * m;
            float ym = tg[it * W_] * m;
            float lx  = fmaxf(__logf(xm), -100.0f);
            float l1x = fmaxf(__logf(1.0f - xm), -100.0f);
            acc += ym * lx + (1.0f - ym) * l1x;  // term, same convention
        }
    }

    // warp reduce
#pragma unroll
    for (int o = 16; o > 0; o >>= 1)
        acc += __shfl_down_sync(0xffffffffu, acc, o);
    if ((tid & 31) == 0) s_wsum[tid >> 5] = acc;
    __syncthreads();

    if (tid < 32) {
        float s = s_wsum[tid];
#pragma unroll
        for (int o = 16; o > 0; o >>= 1)
            s += __shfl_down_sync(0xffffffffu, s, o);
        if (tid == 0) {
            atomicAdd(&g_acc, (double)s);        // g_acc = sum(terms)
            __threadfence();
            unsigned old = atomicAdd(&g_count, 1u);
            s_last = (old == GRID_ - 1) ? 1 : 0;
        }
    }
    __syncthreads();

    if (s_last) {
        double a = g_acc;   // all adds visible: fence + counter protocol
        float loss = (float)(-a / (double)NPIX); // loss = -mean(terms)
        for (int i = tid; i < out_n; i += 1024)
            out[i] = loss;
        if (tid == 0) {     // reset for next graph replay
            g_acc = 0.0;
            g_count = 0u;
        }
    }
}

extern "C" void kernel_launch(void* const* d_in, const int* in_sizes, int n_in,
                              void* d_out, int out_size) {
    const float* centers = (const float*)d_in[0];
    const float* radius  = (const float*)d_in[1];
    const float* mask    = (const float*)d_in[2];
    const int*   ind     = (const int*)d_in[3];
    const float* target  = (const float*)d_in[4];
    const float* peak    = (const float*)d_in[5];
    float* out = (float*)d_out;

    gl_fused<<<GRID_, 1024>>>(centers, radius, mask, ind, target, peak,
                              out, out_size);
}

// round 17
// speedup vs baseline: 1.2216x; 1.2216x over previous
#include <cuda_runtime.h>
#include <cuda_bf16.h>
#include <cstdint>

// Problem constants (fixed by setup_inputs)
#define B_   8
#define NCH  32      // centers channels
#define N_   16      // gaussians per (b,k)
#define K_   16
#define H_   128
#define W_   128
#define BK_  (B_ * K_)          // 128
#define HW_  (H_ * W_)          // 16384
#define NPIX ((long long)BK_ * HW_)  // 2097152

#define GRID_ BK_                // one block per (b,k): 128 blocks, single wave

#define LOG2E_F 1.4426950408889634f
#define LN2_F   0.6931471805599453f

// Cross-block accumulator (zero-initialized at module load; reset in-kernel).
__device__ double   g_acc;     // sum of BCE terms (negative values)
__device__ unsigned g_count;

// Packed f32x2 helpers (ptxas never emits FFMA2 from C++; PTX-only).
__device__ __forceinline__ unsigned long long pk2(float lo, float hi) {
    unsigned long long d;
    asm("mov.b64 %0, {%1, %2};" : "=l"(d) : "f"(lo), "f"(hi));
    return d;
}
__device__ __forceinline__ void upk2(float& lo, float& hi, unsigned long long v) {
    asm("mov.b64 {%0, %1}, %2;" : "=f"(lo), "=f"(hi) : "l"(v));
}
__device__ __forceinline__ unsigned long long fma2(unsigned long long a,
                                                   unsigned long long b,
                                                   unsigned long long c) {
    unsigned long long d;
    asm("fma.rn.f32x2 %0, %1, %2, %3;" : "=l"(d) : "l"(a), "l"(b), "l"(c));
    return d;
}
__device__ __forceinline__ unsigned long long add2(unsigned long long a,
                                                   unsigned long long b) {
    unsigned long long d;
    asm("add.rn.f32x2 %0, %1, %2;" : "=l"(d) : "l"(a), "l"(b));
    return d;
}

// ---------------------------------------------------------------------------
// Single fused kernel (R8 — verified session optimum).
// Block = one (b,k), 1024 threads, all 128 rows.
// Separable tables fx[16][128], fy[128][16] in smem; per pixel
//   g = sum_n fy[y][n]*fx[n][x],  p = sigmoid(g), masked BCE, reduce.
// acc accumulates term = y*log(p*m)+(1-y*m)*log(1-p*m) (<=0);
// finalize: loss = -g_acc/NPIX.
// Fast path (m==1), base-2 form: h = -log2e*g, e = 2^h, sp2 = log2(1+e),
//   term = -ln2*(sp2 + (t-1)*h)   [== -(log1p(e^-g) + (1-t)*g)]
// Dot product uses fma.rn.f32x2: 8 FFMA2 over 4 packed accumulators.
// ---------------------------------------------------------------------------
__global__ void __launch_bounds__(1024) gl_fused(
        const float* __restrict__ centers,
        const float* __restrict__ radius,
        const float* __restrict__ mask,
        const int*   __restrict__ ind,
        const float* __restrict__ target,
        const float* __restrict__ peak,
        float* __restrict__ out, int out_n) {
    int bk   = blockIdx.x;
    int tid  = threadIdx.x;
    int x    = tid & 127;
    int ygrp = tid >> 7;            // 0..7, warp-uniform
    int b    = bk >> 4;

    // 16-byte alignment: s_fy is read via 128-bit LDS.
    __shared__ __align__(16) float s_fx[N_ * W_];   // [n][x]   8 KB
    __shared__ __align__(16) float s_fy[H_ * N_];   // [y][n]   8 KB
    __shared__ __align__(16) float s_c[32];         // cx,cy per n
    __shared__ float s_inv;
    __shared__ float s_wsum[32];
    __shared__ int   s_last;

    // Front-batch the 16 target loads; independent of the gather chain, so
    // they fill the memory pipe while ind->centers->exp tables resolve.
    const float* tg = target + (long long)bk * HW_ + (ygrp * 16) * W_ + x;
    float t[16];
#pragma unroll
    for (int it = 0; it < 16; it++)
        t[it] = tg[it * W_];

    int p = ind[bk];
    if (tid < 32) {
        // channel tid of gathered pred, shifted by peak (x even, y odd)
        s_c[tid] = centers[(b * NCH + tid) * HW_ + p] + peak[bk * 2 + (tid & 1)];
    }
    if (tid == 0) {
        float r = radius[b * HW_ + p];
        s_inv = -0.5f / (r * r);
    }
    __syncthreads();

    float inv = s_inv;
    // fx: 2048 entries, 2 per thread
#pragma unroll
    for (int i = tid; i < N_ * W_; i += 1024) {
        int n  = i >> 7;
        int xx = i & 127;
        float d = s_c[2 * n] - (float)xx;
        s_fx[i] = __expf(inv * d * d);
    }
    // fy: 2048 entries, 2 per thread, layout [y][n]
#pragma unroll
    for (int i = tid; i < H_ * N_; i += 1024) {
        int y = i >> 4;
        int n = i & 15;
        float d = s_c[2 * n + 1] - (float)y;
        s_fy[i] = __expf(inv * d * d);
    }
    __syncthreads();

    // fx pre-packed into 8 f32x2 pairs (n, n+1)
    unsigned long long fx2[8];
#pragma unroll
    for (int j = 0; j < 8; j++)
        fx2[j] = pk2(s_fx[(2 * j) * W_ + x], s_fx[(2 * j + 1) * W_ + x]);

    float m = mask[bk];

    float acc = 0.0f;   // sum of terms (negative)
    if (m == 1.0f) {
        // ---- fast path: packed dot + base-2 epilogue ----
#pragma unroll
        for (int it = 0; it < 16; it++) {
            int y = ygrp * 16 + it;              // warp-uniform row
            const ulonglong2* fyp =
                (const ulonglong2*)&s_fy[y * N_]; // packed (n,n+1) pairs
            unsigned long long d0 = 0ull, d1 = 0ull, d2 = 0ull, d3 = 0ull;
            ulonglong2 w0 = fyp[0];
            ulonglong2 w1 = fyp[1];
            ulonglong2 w2 = fyp[2];
            ulonglong2 w3 = fyp[3];
            d0 = fma2(w0.x, fx2[0], d0);
            d1 = fma2(w0.y, fx2[1], d1);
            d2 = fma2(w1.x, fx2[2], d2);
            d3 = fma2(w1.y, fx2[3], d3);
            d0 = fma2(w2.x, fx2[4], d0);
            d1 = fma2(w2.y, fx2[5], d1);
            d2 = fma2(w3.x, fx2[6], d2);
            d3 = fma2(w3.y, fx2[7], d3);
            d0 = add2(d0, d1);
            d2 = add2(d2, d3);
            d0 = add2(d0, d2);
            float glo, ghi;
            upk2(glo, ghi, d0);
            float g = glo + ghi;                 // g > 0

            // base-2 epilogue: h = -log2e*g; e = 2^h; sp2 = log2(1+e)
            float h = -LOG2E_F * g;
            float e = exp2f(h);                  // MUFU.EX2
            float sp2 = __log2f(1.0f + e);       // MUFU.LG2
            // term = -ln2*(sp2 - (1-t)*h) = -ln2*fmaf(t-1, h, sp2)
            float w = fmaf(t[it] - 1.0f, h, sp2);
            acc = fmaf(-LN2_F, w, acc);
        }
    } else {
        // ---- general path (matches reference construction exactly) ----
#pragma unroll
        for (int it = 0; it < 16; it++) {
            int y = ygrp * 16 + it;
            const float4* fy4 = (const float4*)&s_fy[y * N_];
            float g0 = 0.f, g1 = 0.f, g2 = 0.f, g3 = 0.f;
#pragma unroll
            for (int q = 0; q < 4; q++) {
                float4 v = fy4[q];
                float a0, a1;
                upk2(a0, a1, fx2[q * 2]);
                g0 = fmaf(v.x, a0, g0);
                g1 = fmaf(v.y, a1, g1);
                upk2(a0, a1, fx2[q * 2 + 1]);
                g2 = fmaf(v.z, a0, g2);
                g3 = fmaf(v.w, a1, g3);
            }
            float g = (g0 + g1) + (g2 + g3);
            float e  = __expf(-g);
            float pr = 1.0f / (1.0f + e);
            float xm = pr * m;
            float ym = t[it] * m;
            float lx  = fmaxf(__logf(xm), -100.0f);
            float l1x = fmaxf(__logf(1.0f - xm), -100.0f);
            acc += ym * lx + (1.0f - ym) * l1x;  // term, same convention
        }
    }

    // warp reduce
#pragma unroll
    for (int o = 16; o > 0; o >>= 1)
        acc += __shfl_down_sync(0xffffffffu, acc, o);
    if ((tid & 31) == 0) s_wsum[tid >> 5] = acc;
    __syncthreads();

    if (tid < 32) {
        float s = s_wsum[tid];
#pragma unroll
        for (int o = 16; o > 0; o >>= 1)
            s += __shfl_down_sync(0xffffffffu, s, o);
        if (tid == 0) {
            atomicAdd(&g_acc, (double)s);        // g_acc = sum(terms)
            __threadfence();
            unsigned old = atomicAdd(&g_count, 1u);
            s_last = (old == GRID_ - 1) ? 1 : 0;
        }
    }
    __syncthreads();

    if (s_last) {
        double a = g_acc;   // all adds visible: fence + counter protocol
        float loss = (float)(-a / (double)NPIX); // loss = -mean(terms)
        for (int i = tid; i < out_n; i += 1024)
            out[i] = loss;
        if (tid == 0) {     // reset for next graph replay
            g_acc = 0.0;
            g_count = 0u;
        }
    }
}

extern "C" void kernel_launch(void* const* d_in, const int* in_sizes, int n_in,
                              void* d_out, int out_size) {
    const float* centers = (const float*)d_in[0];
    const float* radius  = (const float*)d_in[1];
    const float* mask    = (const float*)d_in[2];
    const int*   ind     = (const int*)d_in[3];
    const float* target  = (const float*)d_in[4];
    const float* peak    = (const float*)d_in[5];
    float* out = (float*)d_out;

    gl_fused<<<GRID_, 1024>>>(centers, radius, mask, ind, target, peak,
                              out, out_size);
}